// round 7
// baseline (speedup 1.0000x reference)
#include <cuda_runtime.h>
#include <math.h>

typedef unsigned long long ull;

// ---------------- problem constants ----------------
#define NT       512     // 16 warps -> 4 per SMSP
#define BT       16      // batch items per block -> 128 blocks
#define T_STEPS  128
#define STATE    115
#define ACT      39
#define CIN      154
#define COUT     116

#define SBUF 132
#define SX   132
#define SA   44

// ---------------- shared memory layout (float offsets) ----------------
#define OW0   0          // padded 156*16 = 2496 (rows 0..114 x, 115 zero, 116..154 act, 155 zero)
#define OW1   2496
#define OW2   3008
#define OW3   5056
#define OW4   13248
#define OW5   21440
#define OW6   23488
#define OW7   24000
#define OW8   24128      // padded 8*128
#define OWR   25152      // 348
#define OB0   25500
#define OB1   25516
#define OB2   25548
#define OB3   25612
#define OB4   25740
#define OB5   25804
#define OB6   25836
#define OB7   25852
#define OB8   25860      // 128 padded
#define OBR   25988
#define OBUFA 25992      // 16*132
#define OBUFB 28104
#define OXS   30216      // cols 115..131 zero
#define OAB   32328      // 16*44, col 39 zero
#define OSCR  33032      // 1024 floats scratch (combines)
#define SMEM_FLOATS 34056
#define SMEM_BYTES  (SMEM_FLOATS * 4)   // 136224 B

struct Params {
    const float* u;
    const float* W[9];
    const float* b[9];
    const float* Wr;
    const float* br;
    float* out;
};

// ---- packed f32x2 helpers ----
__device__ __forceinline__ ull pk2(float x, float y) {
    ull r; asm("mov.b64 %0, {%1, %2};" : "=l"(r) : "f"(x), "f"(y)); return r;
}
__device__ __forceinline__ void upk2(ull v, float& x, float& y) {
    asm("mov.b64 {%0, %1}, %2;" : "=f"(x), "=f"(y) : "l"(v));
}
__device__ __forceinline__ ull fma2(ull a, ull b, ull c) {
    ull d; asm("fma.rn.f32x2 %0, %1, %2, %3;" : "=l"(d) : "l"(a), "l"(b), "l"(c)); return d;
}

__device__ __forceinline__ void cpy_sh(float* dst, const float* __restrict__ src, int n) {
    for (int k = threadIdx.x; k < n; k += NT) dst[k] = src[k];
}

// ---- vectorized layer: og = tid>>4 (up to 32 groups), b = tid&15 ----
template<int FI, int FO, int TO, bool CLIP, bool RESID>
__device__ __forceinline__ void layerV(const float* __restrict__ W,
                                       const float* __restrict__ bias,
                                       const float* __restrict__ in,
                                       float* __restrict__ out) {
    constexpr int OG = FO / TO;
    constexpr int NP = TO / 2;
    const int og = threadIdx.x >> 4;
    const int b  = threadIdx.x & 15;
    if (OG >= 32 || og < OG) {
        const int o0 = og * TO;
        const float* inp = in + b * SBUF;
        ull acc[NP];
        if constexpr (TO == 2) {
            float2 bv = *(const float2*)(bias + o0);
            acc[0] = pk2(bv.x, bv.y);
        } else {
#pragma unroll
            for (int q = 0; q < NP / 2; ++q) {
                float4 bv = *(const float4*)(bias + o0 + 4 * q);
                acc[2 * q]     = pk2(bv.x, bv.y);
                acc[2 * q + 1] = pk2(bv.z, bv.w);
            }
        }
#pragma unroll
        for (int i4 = 0; i4 < FI / 4; ++i4) {
            float4 av = *(const float4*)(inp + 4 * i4);
            float ae[4] = {av.x, av.y, av.z, av.w};
#pragma unroll
            for (int e = 0; e < 4; ++e) {
                const int i = 4 * i4 + e;
                ull aa = pk2(ae[e], ae[e]);
                const float* wr = W + i * FO + o0;
                if constexpr (TO == 2) {
                    acc[0] = fma2(aa, *(const ull*)wr, acc[0]);
                } else {
#pragma unroll
                    for (int q = 0; q < NP / 2; ++q) {
                        ulonglong2 wv = *((const ulonglong2*)wr + q);
                        acc[2 * q]     = fma2(aa, wv.x, acc[2 * q]);
                        acc[2 * q + 1] = fma2(aa, wv.y, acc[2 * q + 1]);
                    }
                }
            }
        }
        float r[TO];
#pragma unroll
        for (int j = 0; j < NP; ++j) upk2(acc[j], r[2 * j], r[2 * j + 1]);
        if constexpr (CLIP) {
#pragma unroll
            for (int j = 0; j < TO; ++j) r[j] = fminf(fmaxf(r[j], 0.0f), 6.0f);
        }
        float* op = out + b * SBUF + o0;
        if constexpr (RESID) {
#pragma unroll
            for (int q = 0; q < TO / 4; ++q) {
                float4 xv = *(const float4*)(op + 4 * q);
                xv.x += r[4 * q]; xv.y += r[4 * q + 1];
                xv.z += r[4 * q + 2]; xv.w += r[4 * q + 3];
                *(float4*)(op + 4 * q) = xv;
            }
        } else if constexpr (TO == 2) {
            *(float2*)op = make_float2(r[0], r[1]);
        } else {
#pragma unroll
            for (int q = 0; q < TO / 4; ++q)
                *(float4*)(op + 4 * q) = make_float4(r[4 * q], r[4 * q + 1],
                                                     r[4 * q + 2], r[4 * q + 3]);
        }
    }
}

// ---- L0 quarter accumulation: NF4 float4 rows, W pre-offset to (row0*16 + o0) ----
template<int NF4>
__device__ __forceinline__ void l0_part(const float* __restrict__ src,
                                        const float* __restrict__ W,
                                        ull& acc) {
#pragma unroll
    for (int i4 = 0; i4 < NF4; ++i4) {
        float4 av = *(const float4*)(src + 4 * i4);
        float ae[4] = {av.x, av.y, av.z, av.w};
#pragma unroll
        for (int e = 0; e < 4; ++e)
            acc = fma2(pk2(ae[e], ae[e]), *(const ull*)(W + (4 * i4 + e) * 16), acc);
    }
}

__global__ void __launch_bounds__(NT, 1) worldnet_kernel(Params p) {
    extern __shared__ float sh[];
    const int tid = threadIdx.x;
    const int b0 = blockIdx.x * BT;
    const int og = tid >> 4;
    const int bb = tid & 15;

    // ---- one-time weight/bias staging ----
    for (int k = tid; k < 156 * 16; k += NT) {            // W0 padded: zero rows 115 & 155
        int r = k >> 4, c = k & 15;
        float v = 0.0f;
        if (r < 115)                  v = p.W[0][r * 16 + c];
        else if (r >= 116 && r < 155) v = p.W[0][(r - 1) * 16 + c];
        sh[OW0 + k] = v;
    }
    cpy_sh(sh + OW1, p.W[1], 16 * 32);
    cpy_sh(sh + OW2, p.W[2], 32 * 64);
    cpy_sh(sh + OW3, p.W[3], 64 * 128);
    cpy_sh(sh + OW4, p.W[4], 128 * 64);
    cpy_sh(sh + OW5, p.W[5], 64 * 32);
    cpy_sh(sh + OW6, p.W[6], 32 * 16);
    cpy_sh(sh + OW7, p.W[7], 16 * 8);
    for (int k = tid; k < 8 * 128; k += NT) {
        int i = k >> 7, o = k & 127;
        sh[OW8 + k] = (o < STATE) ? p.W[8][i * STATE + o] : 0.0f;
    }
    for (int k = tid; k < 348; k += NT)
        sh[OWR + k] = (k < STATE * 3) ? p.Wr[k] : 0.0f;
    cpy_sh(sh + OB0, p.b[0], 16);
    cpy_sh(sh + OB1, p.b[1], 32);
    cpy_sh(sh + OB2, p.b[2], 64);
    cpy_sh(sh + OB3, p.b[3], 128);
    cpy_sh(sh + OB4, p.b[4], 64);
    cpy_sh(sh + OB5, p.b[5], 32);
    cpy_sh(sh + OB6, p.b[6], 16);
    cpy_sh(sh + OB7, p.b[7], 8);
    for (int k = tid; k < 128; k += NT)
        sh[OB8 + k] = (k < STATE) ? p.b[8][k] : 0.0f;
    for (int k = tid; k < 4; k += NT)
        sh[OBR + k] = (k < 3) ? p.br[k] : 0.0f;

    // ---- init x0 (pad cols zero), zero OAB pad col ----
    for (int k = tid; k < BT * SX; k += NT) {
        int b = k / SX, i = k - b * SX;
        sh[OXS + k] = (i < STATE)
            ? p.u[(size_t)(b0 + b) * T_STEPS * CIN + i] : 0.0f;
    }
    if (tid < BT) sh[OAB + tid * SA + ACT] = 0.0f;
    __syncthreads();

    // ---- time loop ----
    for (int t = 0; t < T_STEPS; ++t) {
        // stage actions a_t
        for (int k = tid; k < BT * ACT; k += NT) {
            int b = k / ACT, j = k - b * ACT;
            sh[OAB + b * SA + j] =
                p.u[((size_t)(b0 + b) * T_STEPS + t) * CIN + STATE + j];
        }
        // out[:, t, 0:116] = x_t (col 115 overwritten by reward later)
        for (int k = tid; k < BT * 29; k += NT) {
            int b = k / 29, c = k - b * 29;
            float4 v = *(const float4*)(sh + OXS + b * SX + 4 * c);
            *(float4*)(p.out + ((size_t)(b0 + b) * T_STEPS + t) * COUT + 4 * c) = v;
        }
        __syncthreads();

        // ---- L0: concat(x,a)[156pad] -> 16. 8 pairs x 4 FI-quarters = 32 groups ----
        {
            const int pg = og & 7;
            const int q  = og >> 3;
            const int o0 = pg * 2;
            ull acc;
            if (q == 0) {
                float2 bv = *(const float2*)(sh + OB0 + o0);
                acc = pk2(bv.x, bv.y);
            } else acc = 0ull;
            const float* xr = sh + OXS + bb * SX;
            if (q == 0)      l0_part<10>(xr,        sh + OW0 + o0,            acc);
            else if (q == 1) l0_part<10>(xr + 40,   sh + OW0 + 40 * 16 + o0,  acc);
            else if (q == 2) l0_part< 9>(xr + 80,   sh + OW0 + 80 * 16 + o0,  acc);
            else             l0_part<10>(sh + OAB + bb * SA,
                                         sh + OW0 + 116 * 16 + o0, acc);
            *(ull*)(sh + OSCR + (pg * 16 + bb) * 8 + q * 2) = acc;
        }
        __syncthreads();
        if (tid < 128) {  // combine quarters, clip, write to OBUFB
            const int pg = tid >> 4, b = tid & 15;
            const float* base = sh + OSCR + (pg * 16 + b) * 8;
            ulonglong2 v01 = *(const ulonglong2*)(base);
            ulonglong2 v23 = *(const ulonglong2*)(base + 4);
            float a0, a1, c0, c1, d0, d1, e0, e1;
            upk2(v01.x, a0, a1); upk2(v01.y, c0, c1);
            upk2(v23.x, d0, d1); upk2(v23.y, e0, e1);
            float lo = (a0 + c0) + (d0 + e0);
            float hi = (a1 + c1) + (d1 + e1);
            lo = fminf(fmaxf(lo, 0.0f), 6.0f);
            hi = fminf(fmaxf(hi, 0.0f), 6.0f);
            *(float2*)(sh + OBUFB + b * SBUF + pg * 2) = make_float2(lo, hi);
        }
        __syncthreads();

        layerV<16, 32, 2, true, false>(sh + OW1, sh + OB1, sh + OBUFB, sh + OBUFA); __syncthreads();
        layerV<32, 64, 2, true, false>(sh + OW2, sh + OB2, sh + OBUFA, sh + OBUFB); __syncthreads();
        layerV<64, 128, 4, true, false>(sh + OW3, sh + OB3, sh + OBUFB, sh + OBUFA); __syncthreads();

        // ---- L4: 128 -> 64, TO=4, FI halved -> 32 groups ----
        {
            const int g = og & 15;
            const int h = og >> 4;
            const int o0 = g * 4;
            const int rb = h * 64;
            ull a0, a1;
            if (h == 0) {
                float4 bv = *(const float4*)(sh + OB4 + o0);
                a0 = pk2(bv.x, bv.y); a1 = pk2(bv.z, bv.w);
            } else { a0 = 0ull; a1 = 0ull; }
            const float* inp = sh + OBUFA + bb * SBUF + rb;
#pragma unroll
            for (int i4 = 0; i4 < 16; ++i4) {
                float4 av = *(const float4*)(inp + 4 * i4);
                float ae[4] = {av.x, av.y, av.z, av.w};
#pragma unroll
                for (int e = 0; e < 4; ++e) {
                    ull aa = pk2(ae[e], ae[e]);
                    ulonglong2 wv = *(const ulonglong2*)(sh + OW4 + (rb + 4 * i4 + e) * 64 + o0);
                    a0 = fma2(aa, wv.x, a0);
                    a1 = fma2(aa, wv.y, a1);
                }
            }
            if (h == 1) {
                ulonglong2 s; s.x = a0; s.y = a1;
                *(ulonglong2*)(sh + OSCR + (g * 16 + bb) * 4) = s;
            }
            __syncthreads();
            if (h == 0) {
                ulonglong2 s = *(const ulonglong2*)(sh + OSCR + (g * 16 + bb) * 4);
                float r0, r1, r2, r3, p0, p1, p2, p3;
                upk2(a0, r0, r1); upk2(a1, r2, r3);
                upk2(s.x, p0, p1); upk2(s.y, p2, p3);
                r0 += p0; r1 += p1; r2 += p2; r3 += p3;
                r0 = fminf(fmaxf(r0, 0.0f), 6.0f);
                r1 = fminf(fmaxf(r1, 0.0f), 6.0f);
                r2 = fminf(fmaxf(r2, 0.0f), 6.0f);
                r3 = fminf(fmaxf(r3, 0.0f), 6.0f);
                *(float4*)(sh + OBUFB + bb * SBUF + o0) = make_float4(r0, r1, r2, r3);
            }
            __syncthreads();
        }

        layerV<64, 32, 2, true, false>(sh + OW5, sh + OB5, sh + OBUFB, sh + OBUFA); __syncthreads();
        layerV<32, 16, 2, true, false>(sh + OW6, sh + OB6, sh + OBUFA, sh + OBUFB); __syncthreads();
        layerV<16, 8, 2, true, false>(sh + OW7, sh + OB7, sh + OBUFB, sh + OBUFA); __syncthreads();
        // L8 (8 -> 128 padded) fused with residual: XS += delta
        layerV<8, 128, 4, false, true>(sh + OW8, sh + OB8, sh + OBUFA, sh + OXS); __syncthreads();

        // ---- reward from x_{t+1}: one warp per item ----
        {
            const int b = tid >> 5;
            const int l = tid & 31;
            float p0 = 0.f, p1 = 0.f, p2 = 0.f;
            const float* xr = sh + OXS + b * SX;
            const float* Wr = sh + OWR;
            for (int i = l; i < STATE; i += 32) {
                float v = xr[i];
                p0 = fmaf(v, Wr[3 * i + 0], p0);
                p1 = fmaf(v, Wr[3 * i + 1], p1);
                p2 = fmaf(v, Wr[3 * i + 2], p2);
            }
#pragma unroll
            for (int off = 16; off > 0; off >>= 1) {
                p0 += __shfl_down_sync(0xffffffffu, p0, off);
                p1 += __shfl_down_sync(0xffffffffu, p1, off);
                p2 += __shfl_down_sync(0xffffffffu, p2, off);
            }
            if (l == 0) {
                p0 += sh[OBR + 0]; p1 += sh[OBR + 1]; p2 += sh[OBR + 2];
                p.out[((size_t)(b0 + b) * T_STEPS + t) * COUT + STATE] =
                    -sqrtf(p0 * p0 + p1 * p1 + p2 * p2);
            }
        }
        // no barrier: next-iter top only writes OAB/gmem and reads OXS
    }
}

extern "C" void kernel_launch(void* const* d_in, const int* in_sizes, int n_in,
                              void* d_out, int out_size) {
    Params p;
    p.u = (const float*)d_in[0];
    for (int i = 0; i < 9; ++i) {
        p.W[i] = (const float*)d_in[1 + 2 * i];
        p.b[i] = (const float*)d_in[2 + 2 * i];
    }
    p.Wr = (const float*)d_in[19];
    p.br = (const float*)d_in[20];
    p.out = (float*)d_out;

    cudaFuncSetAttribute(worldnet_kernel,
                         cudaFuncAttributeMaxDynamicSharedMemorySize, SMEM_BYTES);
    worldnet_kernel<<<2048 / BT, NT, SMEM_BYTES>>>(p);
}